// round 5
// baseline (speedup 1.0000x reference)
#include <cuda_runtime.h>
#include <math.h>

// Problem dims
#define SB 8
#define SS 2048
#define SD 1024
#define SG 4096          // 4*D
#define SQD 1024
#define SKD 256
#define SOH 64
#define MTOT (SB*SS)     // 16384

// ---------------- scratch (static device globals; no allocation) -------------
__device__ float g_gxq[(size_t)MTOT * SG];
__device__ float g_gxk[(size_t)MTOT * SG];
__device__ float g_hqs[(size_t)MTOT * SD];
__device__ float g_hks[(size_t)MTOT * SD];
__device__ float g_t1q[(size_t)MTOT * SOH];
__device__ float g_t1k[(size_t)MTOT * SOH];
__device__ float g_h[2][2][SB * SD];         // [lstm][parity][b*D+d]
__device__ volatile int g_bar_count;
__device__ volatile int g_bar_sense;

// ---------------- generic fp32 GEMM: C[M,N] = A[M,K] @ B[N,K]^T + bias -------
__global__ void sgemm_nt(const float* __restrict__ A, const float* __restrict__ Bm,
                         const float* __restrict__ bias, float* __restrict__ C,
                         int M, int N, int K, int relu)
{
    const int BM = 128, BN = 128, BK = 8, TM = 8, TN = 8;
    __shared__ float As[BK][BM];
    __shared__ float Bs[BK][BN];

    int tid = threadIdx.x;
    int bm = blockIdx.y * BM;
    int bn = blockIdx.x * BN;

    int arow = tid >> 1;
    int acol = (tid & 1) * 4;
    int ty = tid >> 4, tx = tid & 15;

    float acc[TM][TN];
    #pragma unroll
    for (int i = 0; i < TM; i++)
        #pragma unroll
        for (int j = 0; j < TN; j++) acc[i][j] = 0.f;

    for (int k0 = 0; k0 < K; k0 += BK) {
        float4 a4 = *(const float4*)(A + (size_t)(bm + arow) * K + k0 + acol);
        As[acol + 0][arow] = a4.x;
        As[acol + 1][arow] = a4.y;
        As[acol + 2][arow] = a4.z;
        As[acol + 3][arow] = a4.w;
        float4 b4 = make_float4(0.f, 0.f, 0.f, 0.f);
        if (bn + arow < N)
            b4 = *(const float4*)(Bm + (size_t)(bn + arow) * K + k0 + acol);
        Bs[acol + 0][arow] = b4.x;
        Bs[acol + 1][arow] = b4.y;
        Bs[acol + 2][arow] = b4.z;
        Bs[acol + 3][arow] = b4.w;
        __syncthreads();

        #pragma unroll
        for (int kk = 0; kk < BK; kk++) {
            float ar[TM], br[TN];
            float4 a0 = *(const float4*)&As[kk][ty * TM];
            float4 a1 = *(const float4*)&As[kk][ty * TM + 4];
            ar[0]=a0.x; ar[1]=a0.y; ar[2]=a0.z; ar[3]=a0.w;
            ar[4]=a1.x; ar[5]=a1.y; ar[6]=a1.z; ar[7]=a1.w;
            float4 b0 = *(const float4*)&Bs[kk][tx * TN];
            float4 b1 = *(const float4*)&Bs[kk][tx * TN + 4];
            br[0]=b0.x; br[1]=b0.y; br[2]=b0.z; br[3]=b0.w;
            br[4]=b1.x; br[5]=b1.y; br[6]=b1.z; br[7]=b1.w;
            #pragma unroll
            for (int i = 0; i < TM; i++)
                #pragma unroll
                for (int j = 0; j < TN; j++)
                    acc[i][j] += ar[i] * br[j];
        }
        __syncthreads();
    }

    #pragma unroll
    for (int i = 0; i < TM; i++) {
        int m = bm + ty * TM + i;
        #pragma unroll
        for (int j = 0; j < TN; j++) {
            int n = bn + tx * TN + j;
            if (n < N) {
                float v = acc[i][j] + bias[n];
                if (relu) v = v > 0.f ? v : 0.f;
                C[(size_t)m * N + n] = v;
            }
        }
    }
}

// ---------------- persistent LSTM recurrence ---------------------------------
__device__ __forceinline__ float sigf(float x) { return 1.f / (1.f + expf(-x)); }

__global__ void __launch_bounds__(256, 2) lstm_persistent(
    const float* __restrict__ hq0, const float* __restrict__ cq0,
    const float* __restrict__ hk0, const float* __restrict__ ck0,
    const float* __restrict__ Wh_q, const float* __restrict__ bh_q,
    const float* __restrict__ Wh_k, const float* __restrict__ bh_k,
    float* __restrict__ out)
{
    __shared__ float hs[SB][SD + 4];
    int cta  = blockIdx.x;
    int lstm = cta >> 7;               // 0=q, 1=k
    int ublk = (cta & 127) * 8;

    const float* Wh  = lstm ? Wh_k : Wh_q;
    const float* bh  = lstm ? bh_k : bh_q;
    const float* gx  = lstm ? g_gxk : g_gxq;
    float*       hss = lstm ? g_hks : g_hqs;
    const float* h0  = lstm ? hk0 : hq0;
    const float* c0  = lstm ? ck0 : cq0;

    int tid = threadIdx.x;
    int w = tid >> 5, lane = tid & 31;
    int u = ublk + w;                  // unit 0..1023
    int gate = lane >> 3, b = lane & 7;
    int r = gate * SD + u;
    float bhr = bh[r];
    const float4* wr = (const float4*)(Wh + (size_t)r * SD);

    float creg = 0.f, hlast = 0.f;
    if (lane < 8) creg = c0[b * SD + u];

    int sense = 0;
    const int nblk = gridDim.x;

    for (int t = 0; t < SS; t++) {
        // stage h into SMEM (L2-coherent loads; addresses repeat every 2 steps)
        const float* hin = (t == 0) ? h0 : g_h[lstm][t & 1];
        for (int i = tid * 4; i < SB * SD; i += 1024) {
            float4 v = __ldcg((const float4*)(hin + i));
            *(float4*)&hs[i >> 10][i & 1023] = v;
        }
        __syncthreads();

        const float4* hb = (const float4*)&hs[b][0];
        float sx = 0.f, sy = 0.f, sz = 0.f, sw = 0.f;
        #pragma unroll 8
        for (int kk = 0; kk < SD / 4; kk++) {
            float4 wv = wr[kk];
            float4 hv = hb[kk];
            sx += wv.x * hv.x;
            sy += wv.y * hv.y;
            sz += wv.z * hv.z;
            sw += wv.w * hv.w;
        }
        float acc = (sx + sy) + (sz + sw) + gx[((size_t)b * SS + t) * SG + r] + bhr;

        unsigned mask = 0xffffffffu;
        float gi = __shfl_sync(mask, acc, b);
        float gf = __shfl_sync(mask, acc, 8 + b);
        float gg = __shfl_sync(mask, acc, 16 + b);
        float go = __shfl_sync(mask, acc, 24 + b);

        if (lane < 8) {
            float cn = sigf(gf) * creg + sigf(gi) * tanhf(gg);
            float hn = sigf(go) * tanhf(cn);
            creg = cn;
            hlast = hn;
            g_h[lstm][(t & 1) ^ 1][b * SD + u] = hn;
            hss[((size_t)b * SS + t) * SD + u] = hn;
            __threadfence();           // publish h (also flushes L1)
        }

        // grid barrier (sense-reversing)
        __syncthreads();
        if (tid == 0) {
            sense ^= 1;
            __threadfence();
            if (atomicAdd((int*)&g_bar_count, 1) == nblk - 1) {
                g_bar_count = 0;
                __threadfence();
                g_bar_sense = sense;
            } else {
                while (g_bar_sense != sense) { }
            }
            __threadfence();
        }
        __syncthreads();
    }

    // final states: out layout = out_q | out_k | hq | cq | hk | ck
    if (lane < 8) {
        const size_t base = (size_t)MTOT * SQD + (size_t)MTOT * SKD;
        out[base + (size_t)lstm * 2 * SB * SD + b * SD + u] = hlast;
        out[base + (size_t)lstm * 2 * SB * SD + SB * SD + b * SD + u] = creg;
    }
}

// ---------------- barrier init -----------------------------------------------
__global__ void init_barrier()
{
    if (threadIdx.x == 0 && blockIdx.x == 0) {
        g_bar_count = 0;
        g_bar_sense = 0;
    }
}

// ---------------- launch ------------------------------------------------------
extern "C" void kernel_launch(void* const* d_in, const int* in_sizes, int n_in,
                              void* d_out, int out_size)
{
    const float* x    = (const float*)d_in[0];
    const float* hq   = (const float*)d_in[1];
    const float* cq   = (const float*)d_in[2];
    const float* hk   = (const float*)d_in[3];
    const float* ck   = (const float*)d_in[4];
    const float* Wi_q = (const float*)d_in[5];
    const float* Wh_q = (const float*)d_in[6];
    const float* bi_q = (const float*)d_in[7];
    const float* bh_q = (const float*)d_in[8];
    const float* Wi_k = (const float*)d_in[9];
    const float* Wh_k = (const float*)d_in[10];
    const float* bi_k = (const float*)d_in[11];
    const float* bh_k = (const float*)d_in[12];
    const float* W1_q = (const float*)d_in[13];
    const float* b1_q = (const float*)d_in[14];
    const float* W2_q = (const float*)d_in[15];
    const float* b2_q = (const float*)d_in[16];
    const float* W1_k = (const float*)d_in[17];
    const float* b1_k = (const float*)d_in[18];
    const float* W2_k = (const float*)d_in[19];
    const float* b2_k = (const float*)d_in[20];
    float* out = (float*)d_out;

    float *gxq, *gxk, *hqs, *hks, *t1q, *t1k;
    cudaGetSymbolAddress((void**)&gxq, g_gxq);
    cudaGetSymbolAddress((void**)&gxk, g_gxk);
    cudaGetSymbolAddress((void**)&hqs, g_hqs);
    cudaGetSymbolAddress((void**)&hks, g_hks);
    cudaGetSymbolAddress((void**)&t1q, g_t1q);
    cudaGetSymbolAddress((void**)&t1k, g_t1k);

    init_barrier<<<1, 32>>>();

    // Hoisted input projections: gx = x @ Wi^T + bi  (M=16384, N=4096, K=1024)
    dim3 ggx(SG / 128, MTOT / 128);
    sgemm_nt<<<ggx, 256>>>(x, Wi_q, bi_q, gxq, MTOT, SG, SD, 0);
    sgemm_nt<<<ggx, 256>>>(x, Wi_k, bi_k, gxk, MTOT, SG, SD, 0);

    // Full recurrence in ONE launch
    lstm_persistent<<<256, 256>>>(hq, cq, hk, ck, Wh_q, bh_q, Wh_k, bh_k, out);

    // Output MLPs
    sgemm_nt<<<dim3(1, MTOT / 128), 256>>>(hqs, W1_q, b1_q, t1q, MTOT, SOH, SD, 1);
    sgemm_nt<<<dim3(SQD / 128, MTOT / 128), 256>>>(t1q, W2_q, b2_q, out, MTOT, SQD, SOH, 0);
    sgemm_nt<<<dim3(1, MTOT / 128), 256>>>(hks, W1_k, b1_k, t1k, MTOT, SOH, SD, 1);
    sgemm_nt<<<dim3(SKD / 128, MTOT / 128), 256>>>(t1k, W2_k, b2_k,
                                                   out + (size_t)MTOT * SQD, MTOT, SKD, SOH, 0);
}

// round 6
// speedup vs baseline: 2.1287x; 2.1287x over previous
#include <cuda_runtime.h>
#include <math.h>

// Problem dims
#define SB 8
#define SS 2048
#define SD 1024
#define SG 4096          // 4*D
#define SQD 1024
#define SKD 256
#define SOH 64
#define MTOT (SB*SS)     // 16384

// ---------------- scratch (static device globals; no allocation) -------------
__device__ float g_gxq[(size_t)MTOT * SG];
__device__ float g_gxk[(size_t)MTOT * SG];
__device__ float g_hqs[(size_t)MTOT * SD];
__device__ float g_hks[(size_t)MTOT * SD];
__device__ float g_t1q[(size_t)MTOT * SOH];
__device__ float g_t1k[(size_t)MTOT * SOH];
__device__ float g_h[2][2][SB * SD];         // [lstm][parity][b*D+d]
__device__ volatile int g_bar_count;
__device__ volatile int g_bar_sense;

// ---------------- generic fp32 GEMM: C[M,N] = A[M,K] @ B[N,K]^T + bias -------
__global__ void sgemm_nt(const float* __restrict__ A, const float* __restrict__ Bm,
                         const float* __restrict__ bias, float* __restrict__ C,
                         int M, int N, int K, int relu)
{
    const int BM = 128, BN = 128, BK = 8, TM = 8, TN = 8;
    __shared__ float As[BK][BM];
    __shared__ float Bs[BK][BN];

    int tid = threadIdx.x;
    int bm = blockIdx.y * BM;
    int bn = blockIdx.x * BN;

    int arow = tid >> 1;
    int acol = (tid & 1) * 4;
    int ty = tid >> 4, tx = tid & 15;

    float acc[TM][TN];
    #pragma unroll
    for (int i = 0; i < TM; i++)
        #pragma unroll
        for (int j = 0; j < TN; j++) acc[i][j] = 0.f;

    for (int k0 = 0; k0 < K; k0 += BK) {
        float4 a4 = *(const float4*)(A + (size_t)(bm + arow) * K + k0 + acol);
        As[acol + 0][arow] = a4.x;
        As[acol + 1][arow] = a4.y;
        As[acol + 2][arow] = a4.z;
        As[acol + 3][arow] = a4.w;
        float4 b4 = make_float4(0.f, 0.f, 0.f, 0.f);
        if (bn + arow < N)
            b4 = *(const float4*)(Bm + (size_t)(bn + arow) * K + k0 + acol);
        Bs[acol + 0][arow] = b4.x;
        Bs[acol + 1][arow] = b4.y;
        Bs[acol + 2][arow] = b4.z;
        Bs[acol + 3][arow] = b4.w;
        __syncthreads();

        #pragma unroll
        for (int kk = 0; kk < BK; kk++) {
            float ar[TM], br[TN];
            float4 a0 = *(const float4*)&As[kk][ty * TM];
            float4 a1 = *(const float4*)&As[kk][ty * TM + 4];
            ar[0]=a0.x; ar[1]=a0.y; ar[2]=a0.z; ar[3]=a0.w;
            ar[4]=a1.x; ar[5]=a1.y; ar[6]=a1.z; ar[7]=a1.w;
            float4 b0 = *(const float4*)&Bs[kk][tx * TN];
            float4 b1 = *(const float4*)&Bs[kk][tx * TN + 4];
            br[0]=b0.x; br[1]=b0.y; br[2]=b0.z; br[3]=b0.w;
            br[4]=b1.x; br[5]=b1.y; br[6]=b1.z; br[7]=b1.w;
            #pragma unroll
            for (int i = 0; i < TM; i++)
                #pragma unroll
                for (int j = 0; j < TN; j++)
                    acc[i][j] += ar[i] * br[j];
        }
        __syncthreads();
    }

    #pragma unroll
    for (int i = 0; i < TM; i++) {
        int m = bm + ty * TM + i;
        #pragma unroll
        for (int j = 0; j < TN; j++) {
            int n = bn + tx * TN + j;
            if (n < N) {
                float v = acc[i][j] + bias[n];
                if (relu) v = v > 0.f ? v : 0.f;
                C[(size_t)m * N + n] = v;
            }
        }
    }
}

// ---------------- persistent LSTM recurrence ---------------------------------
__device__ __forceinline__ float sigf(float x) { return 1.f / (1.f + expf(-x)); }

// Split-butterfly reduction stage: halves the live acc array; after all 5
// stages lane L holds  dot[L] = sum over lanes of partial[lane][L].
template<int N>
__device__ __forceinline__ void reduce_stage(float* acc, int lane, int ofs)
{
    bool hi = (lane & ofs) != 0;
    #pragma unroll
    for (int i = 0; i < N; i++) {
        float send = hi ? acc[i] : acc[i + N];
        float recv = __shfl_xor_sync(0xffffffffu, send, ofs);
        float keep = hi ? acc[i + N] : acc[i];
        acc[i] = keep + recv;
    }
}

__global__ void __launch_bounds__(256, 2) lstm_persistent(
    const float* __restrict__ hq0, const float* __restrict__ cq0,
    const float* __restrict__ hk0, const float* __restrict__ ck0,
    const float* __restrict__ Wh_q, const float* __restrict__ bh_q,
    const float* __restrict__ Wh_k, const float* __restrict__ bh_k,
    float* __restrict__ out)
{
    __shared__ float hs[SB][SD + 4];
    int cta  = blockIdx.x;
    int lstm = cta >> 7;               // 0=q, 1=k
    int ublk = (cta & 127) * 8;

    const float* Wh  = lstm ? Wh_k : Wh_q;
    const float* bh  = lstm ? bh_k : bh_q;
    const float* gx  = lstm ? g_gxk : g_gxq;
    float*       hss = lstm ? g_hks : g_hqs;
    const float* h0  = lstm ? hk0 : hq0;
    const float* c0  = lstm ? ck0 : cq0;

    int tid = threadIdx.x;
    int w = tid >> 5, lane = tid & 31;
    int u = ublk + w;                  // this warp's unit
    int gate = lane >> 3, b = lane & 7;
    int r = gate * SD + u;             // this lane's (gate,b) row for epilogue
    float bhr = bh[r];

    // 4 gate-row base pointers for this unit (lane-offset folded in)
    const float* wbase0 = Wh + ((size_t)(0 * SD + u)) * SD + lane * 4;
    const float* wbase1 = Wh + ((size_t)(1 * SD + u)) * SD + lane * 4;
    const float* wbase2 = Wh + ((size_t)(2 * SD + u)) * SD + lane * 4;
    const float* wbase3 = Wh + ((size_t)(3 * SD + u)) * SD + lane * 4;

    float creg = 0.f, hlast = 0.f;
    if (lane < 8) creg = c0[b * SD + u];

    int sense = 0;
    const int nblk = gridDim.x;
    unsigned mask = 0xffffffffu;

    for (int t = 0; t < SS; t++) {
        const float* hin = (t == 0) ? h0 : g_h[lstm][t & 1];

        // prefetch this lane's gx value early (DRAM stream)
        float gxv = __ldcg(&gx[((size_t)b * SS + t) * SG + r]);

        // stage h into SMEM (L2-coherent loads)
        for (int i = tid * 4; i < SB * SD; i += 1024) {
            float4 v = __ldcg((const float4*)(hin + i));
            *(float4*)&hs[i >> 10][i & 1023] = v;
        }
        __syncthreads();

        // 32 dot-partials per lane: acc[g*8+b] over this lane's k-slices
        float acc[32];
        #pragma unroll
        for (int i = 0; i < 32; i++) acc[i] = 0.f;

        #pragma unroll
        for (int it = 0; it < 8; it++) {
            float4 hv[8];
            #pragma unroll
            for (int bb = 0; bb < 8; bb++)
                hv[bb] = *(const float4*)&hs[bb][it * 128 + lane * 4];

            float4 wv0 = *(const float4*)(wbase0 + it * 128);
            float4 wv1 = *(const float4*)(wbase1 + it * 128);
            float4 wv2 = *(const float4*)(wbase2 + it * 128);
            float4 wv3 = *(const float4*)(wbase3 + it * 128);

            #pragma unroll
            for (int bb = 0; bb < 8; bb++) {
                acc[0 * 8 + bb] += wv0.x * hv[bb].x + wv0.y * hv[bb].y
                                 + wv0.z * hv[bb].z + wv0.w * hv[bb].w;
                acc[1 * 8 + bb] += wv1.x * hv[bb].x + wv1.y * hv[bb].y
                                 + wv1.z * hv[bb].z + wv1.w * hv[bb].w;
                acc[2 * 8 + bb] += wv2.x * hv[bb].x + wv2.y * hv[bb].y
                                 + wv2.z * hv[bb].z + wv2.w * hv[bb].w;
                acc[3 * 8 + bb] += wv3.x * hv[bb].x + wv3.y * hv[bb].y
                                 + wv3.z * hv[bb].z + wv3.w * hv[bb].w;
            }
        }

        // cross-lane reduce: lane L ends with full dot (gate=L>>3, b=L&7)
        reduce_stage<16>(acc, lane, 16);
        reduce_stage<8>(acc, lane, 8);
        reduce_stage<4>(acc, lane, 4);
        reduce_stage<2>(acc, lane, 2);
        reduce_stage<1>(acc, lane, 1);

        float a = acc[0] + gxv + bhr;

        float gi = __shfl_sync(mask, a, b);
        float gf = __shfl_sync(mask, a, 8 + b);
        float gg = __shfl_sync(mask, a, 16 + b);
        float go = __shfl_sync(mask, a, 24 + b);

        if (lane < 8) {
            float cn = sigf(gf) * creg + sigf(gi) * tanhf(gg);
            float hn = sigf(go) * tanhf(cn);
            creg = cn;
            hlast = hn;
            g_h[lstm][(t & 1) ^ 1][b * SD + u] = hn;
            hss[((size_t)b * SS + t) * SD + u] = hn;
        }

        // grid barrier (sense-reversing); threadfence publishes h
        __syncthreads();
        if (tid == 0) {
            sense ^= 1;
            __threadfence();
            if (atomicAdd((int*)&g_bar_count, 1) == nblk - 1) {
                g_bar_count = 0;
                __threadfence();
                g_bar_sense = sense;
            } else {
                while (g_bar_sense != sense) { }
            }
            __threadfence();
        }
        __syncthreads();
    }

    // final states: out layout = out_q | out_k | hq | cq | hk | ck
    if (lane < 8) {
        const size_t base = (size_t)MTOT * SQD + (size_t)MTOT * SKD;
        out[base + (size_t)lstm * 2 * SB * SD + b * SD + u] = hlast;
        out[base + (size_t)lstm * 2 * SB * SD + SB * SD + b * SD + u] = creg;
    }
}

// ---------------- barrier init -----------------------------------------------
__global__ void init_barrier()
{
    if (threadIdx.x == 0 && blockIdx.x == 0) {
        g_bar_count = 0;
        g_bar_sense = 0;
    }
}

// ---------------- launch ------------------------------------------------------
extern "C" void kernel_launch(void* const* d_in, const int* in_sizes, int n_in,
                              void* d_out, int out_size)
{
    const float* x    = (const float*)d_in[0];
    const float* hq   = (const float*)d_in[1];
    const float* cq   = (const float*)d_in[2];
    const float* hk   = (const float*)d_in[3];
    const float* ck   = (const float*)d_in[4];
    const float* Wi_q = (const float*)d_in[5];
    const float* Wh_q = (const float*)d_in[6];
    const float* bi_q = (const float*)d_in[7];
    const float* bh_q = (const float*)d_in[8];
    const float* Wi_k = (const float*)d_in[9];
    const float* Wh_k = (const float*)d_in[10];
    const float* bi_k = (const float*)d_in[11];
    const float* bh_k = (const float*)d_in[12];
    const float* W1_q = (const float*)d_in[13];
    const float* b1_q = (const float*)d_in[14];
    const float* W2_q = (const float*)d_in[15];
    const float* b2_q = (const float*)d_in[16];
    const float* W1_k = (const float*)d_in[17];
    const float* b1_k = (const float*)d_in[18];
    const float* W2_k = (const float*)d_in[19];
    const float* b2_k = (const float*)d_in[20];
    float* out = (float*)d_out;

    float *gxq, *gxk, *hqs, *hks, *t1q, *t1k;
    cudaGetSymbolAddress((void**)&gxq, g_gxq);
    cudaGetSymbolAddress((void**)&gxk, g_gxk);
    cudaGetSymbolAddress((void**)&hqs, g_hqs);
    cudaGetSymbolAddress((void**)&hks, g_hks);
    cudaGetSymbolAddress((void**)&t1q, g_t1q);
    cudaGetSymbolAddress((void**)&t1k, g_t1k);

    init_barrier<<<1, 32>>>();

    // Hoisted input projections: gx = x @ Wi^T + bi  (M=16384, N=4096, K=1024)
    dim3 ggx(SG / 128, MTOT / 128);
    sgemm_nt<<<ggx, 256>>>(x, Wi_q, bi_q, gxq, MTOT, SG, SD, 0);
    sgemm_nt<<<ggx, 256>>>(x, Wi_k, bi_k, gxk, MTOT, SG, SD, 0);

    // Full recurrence in ONE launch
    lstm_persistent<<<256, 256>>>(hq, cq, hk, ck, Wh_q, bh_q, Wh_k, bh_k, out);

    // Output MLPs
    sgemm_nt<<<dim3(1, MTOT / 128), 256>>>(hqs, W1_q, b1_q, t1q, MTOT, SOH, SD, 1);
    sgemm_nt<<<dim3(SQD / 128, MTOT / 128), 256>>>(t1q, W2_q, b2_q, out, MTOT, SQD, SOH, 0);
    sgemm_nt<<<dim3(1, MTOT / 128), 256>>>(hks, W1_k, b1_k, t1k, MTOT, SOH, SD, 1);
    sgemm_nt<<<dim3(SKD / 128, MTOT / 128), 256>>>(t1k, W2_k, b2_k,
                                                   out + (size_t)MTOT * SQD, MTOT, SKD, SOH, 0);
}

// round 7
// speedup vs baseline: 2.6339x; 1.2373x over previous
#include <cuda_runtime.h>
#include <math.h>
#include <stdint.h>

// Problem dims
#define SB 8
#define SS 2048
#define SD 1024
#define SG 4096          // 4*D
#define SQD 1024
#define SKD 256
#define SOH 64
#define MTOT (SB*SS)     // 16384

// ---------------- scratch (static device globals; no allocation) -------------
__device__ float g_gxq[(size_t)MTOT * SG];
__device__ float g_gxk[(size_t)MTOT * SG];
__device__ float g_hqs[(size_t)MTOT * SD];
__device__ float g_hks[(size_t)MTOT * SD];
__device__ float g_t1q[(size_t)MTOT * SOH];
__device__ float g_t1k[(size_t)MTOT * SOH];
__device__ float g_h[2][2][SB * SD];         // [lstm][parity][b*D+d]
__device__ volatile int g_bar_count;
__device__ volatile int g_bar_sense;

// ---------------- tf32 tensor-core GEMM: C[M,N]=A[M,K]@B[N,K]^T + bias -------
// CTA tile 128x128x16, 256 threads = 8 warps (2 M x 4 N), warp tile 64x32.
// mma.sync.aligned.m16n8k8.row.col.f32.tf32.tf32.f32
// SMEM row stride 20 floats -> all fragment LDS are bank-conflict-free.
// Requires: M % 128 == 0, K % 16 == 0. N guarded.

__device__ __forceinline__ uint32_t f2tf32(float x)
{
    uint32_t u;
    asm("cvt.rna.tf32.f32 %0, %1;" : "=r"(u) : "f"(x));
    return u;
}

__device__ __forceinline__ void mma_tf32(float* d, const uint32_t* a, const uint32_t* b)
{
    asm volatile(
        "mma.sync.aligned.m16n8k8.row.col.f32.tf32.tf32.f32 "
        "{%0,%1,%2,%3}, {%4,%5,%6,%7}, {%8,%9}, {%0,%1,%2,%3};"
        : "+f"(d[0]), "+f"(d[1]), "+f"(d[2]), "+f"(d[3])
        : "r"(a[0]), "r"(a[1]), "r"(a[2]), "r"(a[3]), "r"(b[0]), "r"(b[1]));
}

#define TSTR 20   // smem row stride (floats)

__global__ void __launch_bounds__(256) tf32gemm_nt(
    const float* __restrict__ A, const float* __restrict__ Bm,
    const float* __restrict__ bias, float* __restrict__ C,
    int M, int N, int K, int relu)
{
    __shared__ uint32_t As[2][128 * TSTR];
    __shared__ uint32_t Bs[2][128 * TSTR];

    int tid = threadIdx.x, wid = tid >> 5, lane = tid & 31;
    int wm = wid & 1, wn = wid >> 1;        // warp coords: 2 x 4
    int bm = blockIdx.y * 128, bn = blockIdx.x * 128;
    int gid = lane >> 2, tig = lane & 3;

    float acc[4][4][4];
    #pragma unroll
    for (int mt = 0; mt < 4; mt++)
        #pragma unroll
        for (int nt = 0; nt < 4; nt++)
            #pragma unroll
            for (int i = 0; i < 4; i++) acc[mt][nt][i] = 0.f;

    // gmem tile-load lambda-ish: each thread loads 2 float4 from A, 2 from B
    // float4 id = i*256+tid (512 total); row = id>>2, c4 = id&3
    int r0 = tid >> 2, c4 = (tid & 3) * 4;          // i=0: rows 0..63
    int r1 = (256 + tid) >> 2;                       // i=1: rows 64..127

    uint32_t pa[8], pb[8];

    int nk = K / 16;

    // prologue: load k-tile 0
    {
        const float* Ap = A + (size_t)(bm + r0) * K + c4;
        const float* Aq = A + (size_t)(bm + r1) * K + c4;
        float4 a0 = *(const float4*)Ap;
        float4 a1 = *(const float4*)Aq;
        pa[0]=f2tf32(a0.x); pa[1]=f2tf32(a0.y); pa[2]=f2tf32(a0.z); pa[3]=f2tf32(a0.w);
        pa[4]=f2tf32(a1.x); pa[5]=f2tf32(a1.y); pa[6]=f2tf32(a1.z); pa[7]=f2tf32(a1.w);
        float4 b0 = make_float4(0.f,0.f,0.f,0.f), b1 = b0;
        if (bn + r0 < N) b0 = *(const float4*)(Bm + (size_t)(bn + r0) * K + c4);
        if (bn + r1 < N) b1 = *(const float4*)(Bm + (size_t)(bn + r1) * K + c4);
        pb[0]=f2tf32(b0.x); pb[1]=f2tf32(b0.y); pb[2]=f2tf32(b0.z); pb[3]=f2tf32(b0.w);
        pb[4]=f2tf32(b1.x); pb[5]=f2tf32(b1.y); pb[6]=f2tf32(b1.z); pb[7]=f2tf32(b1.w);
        #pragma unroll
        for (int j = 0; j < 4; j++) {
            As[0][r0 * TSTR + c4 + j] = pa[j];
            As[0][r1 * TSTR + c4 + j] = pa[4 + j];
            Bs[0][r0 * TSTR + c4 + j] = pb[j];
            Bs[0][r1 * TSTR + c4 + j] = pb[4 + j];
        }
    }
    __syncthreads();

    for (int kt = 0; kt < nk; kt++) {
        int cur = kt & 1;

        // prefetch next k-tile into regs
        if (kt + 1 < nk) {
            int kof = (kt + 1) * 16;
            const float* Ap = A + (size_t)(bm + r0) * K + kof + c4;
            const float* Aq = A + (size_t)(bm + r1) * K + kof + c4;
            float4 a0 = *(const float4*)Ap;
            float4 a1 = *(const float4*)Aq;
            pa[0]=f2tf32(a0.x); pa[1]=f2tf32(a0.y); pa[2]=f2tf32(a0.z); pa[3]=f2tf32(a0.w);
            pa[4]=f2tf32(a1.x); pa[5]=f2tf32(a1.y); pa[6]=f2tf32(a1.z); pa[7]=f2tf32(a1.w);
            float4 b0 = make_float4(0.f,0.f,0.f,0.f), b1 = b0;
            if (bn + r0 < N) b0 = *(const float4*)(Bm + (size_t)(bn + r0) * K + kof + c4);
            if (bn + r1 < N) b1 = *(const float4*)(Bm + (size_t)(bn + r1) * K + kof + c4);
            pb[0]=f2tf32(b0.x); pb[1]=f2tf32(b0.y); pb[2]=f2tf32(b0.z); pb[3]=f2tf32(b0.w);
            pb[4]=f2tf32(b1.x); pb[5]=f2tf32(b1.y); pb[6]=f2tf32(b1.z); pb[7]=f2tf32(b1.w);
        }

        // compute: 2 k-steps of 8
        #pragma unroll
        for (int ks = 0; ks < 2; ks++) {
            uint32_t af[4][4], bf[4][2];
            #pragma unroll
            for (int mt = 0; mt < 4; mt++) {
                int m = wm * 64 + mt * 16;
                const uint32_t* s = &As[cur][0];
                af[mt][0] = s[(m + gid)     * TSTR + ks * 8 + tig];
                af[mt][1] = s[(m + gid + 8) * TSTR + ks * 8 + tig];
                af[mt][2] = s[(m + gid)     * TSTR + ks * 8 + tig + 4];
                af[mt][3] = s[(m + gid + 8) * TSTR + ks * 8 + tig + 4];
            }
            #pragma unroll
            for (int nt = 0; nt < 4; nt++) {
                int n = wn * 32 + nt * 8;
                const uint32_t* s = &Bs[cur][0];
                bf[nt][0] = s[(n + gid) * TSTR + ks * 8 + tig];
                bf[nt][1] = s[(n + gid) * TSTR + ks * 8 + tig + 4];
            }
            #pragma unroll
            for (int mt = 0; mt < 4; mt++)
                #pragma unroll
                for (int nt = 0; nt < 4; nt++)
                    mma_tf32(acc[mt][nt], af[mt], bf[nt]);
        }

        // stage prefetched tile into the other buffer
        if (kt + 1 < nk) {
            int nxt = cur ^ 1;
            #pragma unroll
            for (int j = 0; j < 4; j++) {
                As[nxt][r0 * TSTR + c4 + j] = pa[j];
                As[nxt][r1 * TSTR + c4 + j] = pa[4 + j];
                Bs[nxt][r0 * TSTR + c4 + j] = pb[j];
                Bs[nxt][r1 * TSTR + c4 + j] = pb[4 + j];
            }
            __syncthreads();
        }
    }

    // epilogue
    #pragma unroll
    for (int mt = 0; mt < 4; mt++) {
        #pragma unroll
        for (int nt = 0; nt < 4; nt++) {
            int mrow0 = bm + wm * 64 + mt * 16 + gid;
            int ncol  = bn + wn * 32 + nt * 8 + tig * 2;
            if (ncol < N) {
                float bv0 = bias[ncol], bv1 = bias[ncol + 1];
                float v0 = acc[mt][nt][0] + bv0;
                float v1 = acc[mt][nt][1] + bv1;
                float v2 = acc[mt][nt][2] + bv0;
                float v3 = acc[mt][nt][3] + bv1;
                if (relu) {
                    v0 = v0 > 0.f ? v0 : 0.f;  v1 = v1 > 0.f ? v1 : 0.f;
                    v2 = v2 > 0.f ? v2 : 0.f;  v3 = v3 > 0.f ? v3 : 0.f;
                }
                *(float2*)&C[(size_t)mrow0 * N + ncol]       = make_float2(v0, v1);
                *(float2*)&C[(size_t)(mrow0 + 8) * N + ncol] = make_float2(v2, v3);
            }
        }
    }
}

// ---------------- persistent LSTM recurrence ---------------------------------
__device__ __forceinline__ float sigf(float x) { return 1.f / (1.f + expf(-x)); }

template<int N>
__device__ __forceinline__ void reduce_stage(float* acc, int lane, int ofs)
{
    bool hi = (lane & ofs) != 0;
    #pragma unroll
    for (int i = 0; i < N; i++) {
        float send = hi ? acc[i] : acc[i + N];
        float recv = __shfl_xor_sync(0xffffffffu, send, ofs);
        float keep = hi ? acc[i + N] : acc[i];
        acc[i] = keep + recv;
    }
}

__global__ void __launch_bounds__(256, 2) lstm_persistent(
    const float* __restrict__ hq0, const float* __restrict__ cq0,
    const float* __restrict__ hk0, const float* __restrict__ ck0,
    const float* __restrict__ Wh_q, const float* __restrict__ bh_q,
    const float* __restrict__ Wh_k, const float* __restrict__ bh_k,
    float* __restrict__ out)
{
    __shared__ float hs[SB][SD + 4];
    int cta  = blockIdx.x;
    int lstm = cta >> 7;
    int ublk = (cta & 127) * 8;

    const float* Wh  = lstm ? Wh_k : Wh_q;
    const float* bh  = lstm ? bh_k : bh_q;
    const float* gx  = lstm ? g_gxk : g_gxq;
    float*       hss = lstm ? g_hks : g_hqs;
    const float* h0  = lstm ? hk0 : hq0;
    const float* c0  = lstm ? ck0 : cq0;

    int tid = threadIdx.x;
    int w = tid >> 5, lane = tid & 31;
    int u = ublk + w;
    int gate = lane >> 3, b = lane & 7;
    int r = gate * SD + u;
    float bhr = bh[r];

    const float* wbase0 = Wh + ((size_t)(0 * SD + u)) * SD + lane * 4;
    const float* wbase1 = Wh + ((size_t)(1 * SD + u)) * SD + lane * 4;
    const float* wbase2 = Wh + ((size_t)(2 * SD + u)) * SD + lane * 4;
    const float* wbase3 = Wh + ((size_t)(3 * SD + u)) * SD + lane * 4;

    float creg = 0.f, hlast = 0.f;
    if (lane < 8) creg = c0[b * SD + u];

    int sense = 0;
    const int nblk = gridDim.x;
    unsigned mask = 0xffffffffu;

    for (int t = 0; t < SS; t++) {
        const float* hin = (t == 0) ? h0 : g_h[lstm][t & 1];

        float gxv = __ldcg(&gx[((size_t)b * SS + t) * SG + r]);

        for (int i = tid * 4; i < SB * SD; i += 1024) {
            float4 v = __ldcg((const float4*)(hin + i));
            *(float4*)&hs[i >> 10][i & 1023] = v;
        }
        __syncthreads();

        float acc[32];
        #pragma unroll
        for (int i = 0; i < 32; i++) acc[i] = 0.f;

        #pragma unroll
        for (int it = 0; it < 8; it++) {
            float4 hv[8];
            #pragma unroll
            for (int bb = 0; bb < 8; bb++)
                hv[bb] = *(const float4*)&hs[bb][it * 128 + lane * 4];

            float4 wv0 = *(const float4*)(wbase0 + it * 128);
            float4 wv1 = *(const float4*)(wbase1 + it * 128);
            float4 wv2 = *(const float4*)(wbase2 + it * 128);
            float4 wv3 = *(const float4*)(wbase3 + it * 128);

            #pragma unroll
            for (int bb = 0; bb < 8; bb++) {
                acc[0 * 8 + bb] += wv0.x * hv[bb].x + wv0.y * hv[bb].y
                                 + wv0.z * hv[bb].z + wv0.w * hv[bb].w;
                acc[1 * 8 + bb] += wv1.x * hv[bb].x + wv1.y * hv[bb].y
                                 + wv1.z * hv[bb].z + wv1.w * hv[bb].w;
                acc[2 * 8 + bb] += wv2.x * hv[bb].x + wv2.y * hv[bb].y
                                 + wv2.z * hv[bb].z + wv2.w * hv[bb].w;
                acc[3 * 8 + bb] += wv3.x * hv[bb].x + wv3.y * hv[bb].y
                                 + wv3.z * hv[bb].z + wv3.w * hv[bb].w;
            }
        }

        reduce_stage<16>(acc, lane, 16);
        reduce_stage<8>(acc, lane, 8);
        reduce_stage<4>(acc, lane, 4);
        reduce_stage<2>(acc, lane, 2);
        reduce_stage<1>(acc, lane, 1);

        float a = acc[0] + gxv + bhr;

        float gi = __shfl_sync(mask, a, b);
        float gf = __shfl_sync(mask, a, 8 + b);
        float gg = __shfl_sync(mask, a, 16 + b);
        float go = __shfl_sync(mask, a, 24 + b);

        if (lane < 8) {
            float cn = sigf(gf) * creg + sigf(gi) * tanhf(gg);
            float hn = sigf(go) * tanhf(cn);
            creg = cn;
            hlast = hn;
            g_h[lstm][(t & 1) ^ 1][b * SD + u] = hn;
            hss[((size_t)b * SS + t) * SD + u] = hn;
        }

        __syncthreads();
        if (tid == 0) {
            sense ^= 1;
            __threadfence();
            if (atomicAdd((int*)&g_bar_count, 1) == nblk - 1) {
                g_bar_count = 0;
                __threadfence();
                g_bar_sense = sense;
            } else {
                while (g_bar_sense != sense) { }
            }
            __threadfence();
        }
        __syncthreads();
    }

    if (lane < 8) {
        const size_t base = (size_t)MTOT * SQD + (size_t)MTOT * SKD;
        out[base + (size_t)lstm * 2 * SB * SD + b * SD + u] = hlast;
        out[base + (size_t)lstm * 2 * SB * SD + SB * SD + b * SD + u] = creg;
    }
}

// ---------------- barrier init -----------------------------------------------
__global__ void init_barrier()
{
    if (threadIdx.x == 0 && blockIdx.x == 0) {
        g_bar_count = 0;
        g_bar_sense = 0;
    }
}

// ---------------- launch ------------------------------------------------------
extern "C" void kernel_launch(void* const* d_in, const int* in_sizes, int n_in,
                              void* d_out, int out_size)
{
    const float* x    = (const float*)d_in[0];
    const float* hq   = (const float*)d_in[1];
    const float* cq   = (const float*)d_in[2];
    const float* hk   = (const float*)d_in[3];
    const float* ck   = (const float*)d_in[4];
    const float* Wi_q = (const float*)d_in[5];
    const float* Wh_q = (const float*)d_in[6];
    const float* bi_q = (const float*)d_in[7];
    const float* bh_q = (const float*)d_in[8];
    const float* Wi_k = (const float*)d_in[9];
    const float* Wh_k = (const float*)d_in[10];
    const float* bi_k = (const float*)d_in[11];
    const float* bh_k = (const float*)d_in[12];
    const float* W1_q = (const float*)d_in[13];
    const float* b1_q = (const float*)d_in[14];
    const float* W2_q = (const float*)d_in[15];
    const float* b2_q = (const float*)d_in[16];
    const float* W1_k = (const float*)d_in[17];
    const float* b1_k = (const float*)d_in[18];
    const float* W2_k = (const float*)d_in[19];
    const float* b2_k = (const float*)d_in[20];
    float* out = (float*)d_out;

    float *gxq, *gxk, *hqs, *hks, *t1q, *t1k;
    cudaGetSymbolAddress((void**)&gxq, g_gxq);
    cudaGetSymbolAddress((void**)&gxk, g_gxk);
    cudaGetSymbolAddress((void**)&hqs, g_hqs);
    cudaGetSymbolAddress((void**)&hks, g_hks);
    cudaGetSymbolAddress((void**)&t1q, g_t1q);
    cudaGetSymbolAddress((void**)&t1k, g_t1k);

    init_barrier<<<1, 32>>>();

    // Hoisted input projections: gx = x @ Wi^T + bi  (M=16384, N=4096, K=1024)
    dim3 ggx(SG / 128, MTOT / 128);
    tf32gemm_nt<<<ggx, 256>>>(x, Wi_q, bi_q, gxq, MTOT, SG, SD, 0);
    tf32gemm_nt<<<ggx, 256>>>(x, Wi_k, bi_k, gxk, MTOT, SG, SD, 0);

    // Full recurrence in ONE launch
    lstm_persistent<<<256, 256>>>(hq, cq, hk, ck, Wh_q, bh_q, Wh_k, bh_k, out);

    // Output MLPs
    tf32gemm_nt<<<dim3(1, MTOT / 128), 256>>>(hqs, W1_q, b1_q, t1q, MTOT, SOH, SD, 1);
    tf32gemm_nt<<<dim3(SQD / 128, MTOT / 128), 256>>>(t1q, W2_q, b2_q, out, MTOT, SQD, SOH, 0);
    tf32gemm_nt<<<dim3(1, MTOT / 128), 256>>>(hks, W1_k, b1_k, t1k, MTOT, SOH, SD, 1);
    tf32gemm_nt<<<dim3(SKD / 128, MTOT / 128), 256>>>(t1k, W2_k, b2_k,
                                                      out + (size_t)MTOT * SQD, MTOT, SKD, SOH, 0);
}

// round 8
// speedup vs baseline: 2.7775x; 1.0545x over previous
#include <cuda_runtime.h>
#include <math.h>
#include <stdint.h>

// Problem dims
#define SB 8
#define SS 2048
#define SD 1024
#define SG 4096          // 4*D
#define SQD 1024
#define SKD 256
#define SOH 64
#define MTOT (SB*SS)     // 16384

// ---------------- scratch (static device globals; no allocation) -------------
__device__ float g_gxq[(size_t)MTOT * SG];
__device__ float g_gxk[(size_t)MTOT * SG];
__device__ float g_hqs[(size_t)MTOT * SD];
__device__ float g_hks[(size_t)MTOT * SD];
__device__ float g_t1q[(size_t)MTOT * SOH];
__device__ float g_t1k[(size_t)MTOT * SOH];
__device__ float g_xr[(size_t)MTOT * SD];    // tf32-rounded x
__device__ float g_wq[(size_t)SG * SD];      // tf32-rounded Wi_q
__device__ float g_wk[(size_t)SG * SD];      // tf32-rounded Wi_k
__device__ float g_h[2][2][SB * SD];
__device__ volatile int g_bar_count;
__device__ volatile int g_bar_sense;

// ---------------- helpers -----------------------------------------------------
__device__ __forceinline__ uint32_t f2tf32(float x)
{
    uint32_t u;
    asm("cvt.rna.tf32.f32 %0, %1;" : "=r"(u) : "f"(x));
    return u;
}

__device__ __forceinline__ void mma_tf32(float* d, const uint32_t* a, const uint32_t* b)
{
    asm volatile(
        "mma.sync.aligned.m16n8k8.row.col.f32.tf32.tf32.f32 "
        "{%0,%1,%2,%3}, {%4,%5,%6,%7}, {%8,%9}, {%0,%1,%2,%3};"
        : "+f"(d[0]), "+f"(d[1]), "+f"(d[2]), "+f"(d[3])
        : "r"(a[0]), "r"(a[1]), "r"(a[2]), "r"(a[3]), "r"(b[0]), "r"(b[1]));
}

__device__ __forceinline__ uint32_t smem_u32(const void* p)
{
    return (uint32_t)__cvta_generic_to_shared(p);
}

#define CP_ASYNC16(dst, src) \
    asm volatile("cp.async.cg.shared.global [%0], [%1], 16;" :: "r"(dst), "l"(src))
#define CP_COMMIT() asm volatile("cp.async.commit_group;")
#define CP_WAIT1()  asm volatile("cp.async.wait_group 1;")

// ---------------- elementwise tf32 rounding ----------------------------------
__global__ void round_tf32_k(const float4* __restrict__ in, float4* __restrict__ out, int n4)
{
    int i = blockIdx.x * blockDim.x + threadIdx.x;
    if (i < n4) {
        float4 v = in[i];
        v.x = __uint_as_float(f2tf32(v.x));
        v.y = __uint_as_float(f2tf32(v.y));
        v.z = __uint_as_float(f2tf32(v.z));
        v.w = __uint_as_float(f2tf32(v.w));
        out[i] = v;
    }
}

// ---------------- pipelined tf32 GEMM: C[M,N]=A[M,K]@B[N,K]^T + bias ---------
// 128x128x32 tile, 3-stage cp.async pipeline, 8 warps (2M x 4N), warp 64x32.
// CVT=0: inputs already tf32-rounded. CVT=1: cvt at fragment load.
// Requires M%128==0, K%32==0. N guarded.
#define STAGES 3
#define GBK 32
#define STR 36   // smem row stride (words); banks (4g+t)%32 conflict-free

template<int CVT>
__global__ void __launch_bounds__(256, 2) tf32gemm_pipe(
    const float* __restrict__ A, const float* __restrict__ Bm,
    const float* __restrict__ bias, float* __restrict__ C,
    int M, int N, int K, int relu)
{
    __shared__ uint32_t As[STAGES][128 * STR];
    __shared__ uint32_t Bs[STAGES][128 * STR];

    int tid = threadIdx.x, wid = tid >> 5, lane = tid & 31;
    int wm = wid & 1, wn = wid >> 1;
    int bm = blockIdx.y * 128, bn = blockIdx.x * 128;
    int gid = lane >> 2, tig = lane & 3;

    int r0 = tid >> 3;            // base row (0..31), +32*j
    int c4 = (tid & 7) * 4;       // float offset within 32-wide k-tile

    float acc[4][4][4];
    #pragma unroll
    for (int mt = 0; mt < 4; mt++)
        #pragma unroll
        for (int nt = 0; nt < 4; nt++)
            #pragma unroll
            for (int i = 0; i < 4; i++) acc[mt][nt][i] = 0.f;

    int nk = K / GBK;

    auto issue = [&](int s, int kt) {
        int kof = kt * GBK;
        #pragma unroll
        for (int j = 0; j < 4; j++) {
            int row = r0 + 32 * j;
            uint32_t da = smem_u32(&As[s][row * STR + c4]);
            CP_ASYNC16(da, A + (size_t)(bm + row) * K + kof + c4);
            if (bn + row < N) {
                uint32_t db = smem_u32(&Bs[s][row * STR + c4]);
                CP_ASYNC16(db, Bm + (size_t)(bn + row) * K + kof + c4);
            }
        }
    };

    issue(0, 0); CP_COMMIT();
    issue(1, 1); CP_COMMIT();

    for (int kt = 0; kt < nk; kt++) {
        CP_WAIT1();
        __syncthreads();

        if (kt + 2 < nk) issue((kt + 2) % STAGES, kt + 2);
        CP_COMMIT();

        int s = kt % STAGES;
        const uint32_t* sa = &As[s][0];
        const uint32_t* sb = &Bs[s][0];

        #pragma unroll
        for (int ks = 0; ks < 4; ks++) {
            uint32_t af[4][4], bf[4][2];
            #pragma unroll
            for (int mt = 0; mt < 4; mt++) {
                int m = wm * 64 + mt * 16;
                af[mt][0] = sa[(m + gid)     * STR + ks * 8 + tig];
                af[mt][1] = sa[(m + gid + 8) * STR + ks * 8 + tig];
                af[mt][2] = sa[(m + gid)     * STR + ks * 8 + tig + 4];
                af[mt][3] = sa[(m + gid + 8) * STR + ks * 8 + tig + 4];
            }
            #pragma unroll
            for (int nt = 0; nt < 4; nt++) {
                int n = wn * 32 + nt * 8;
                bf[nt][0] = sb[(n + gid) * STR + ks * 8 + tig];
                bf[nt][1] = sb[(n + gid) * STR + ks * 8 + tig + 4];
            }
            if (CVT) {
                #pragma unroll
                for (int mt = 0; mt < 4; mt++)
                    #pragma unroll
                    for (int i = 0; i < 4; i++)
                        af[mt][i] = f2tf32(__uint_as_float(af[mt][i]));
                #pragma unroll
                for (int nt = 0; nt < 4; nt++) {
                    bf[nt][0] = f2tf32(__uint_as_float(bf[nt][0]));
                    bf[nt][1] = f2tf32(__uint_as_float(bf[nt][1]));
                }
            }
            #pragma unroll
            for (int mt = 0; mt < 4; mt++)
                #pragma unroll
                for (int nt = 0; nt < 4; nt++)
                    mma_tf32(acc[mt][nt], af[mt], bf[nt]);
        }
    }

    #pragma unroll
    for (int mt = 0; mt < 4; mt++) {
        #pragma unroll
        for (int nt = 0; nt < 4; nt++) {
            int mrow0 = bm + wm * 64 + mt * 16 + gid;
            int ncol  = bn + wn * 32 + nt * 8 + tig * 2;
            if (ncol < N) {
                float bv0 = bias[ncol], bv1 = bias[ncol + 1];
                float v0 = acc[mt][nt][0] + bv0;
                float v1 = acc[mt][nt][1] + bv1;
                float v2 = acc[mt][nt][2] + bv0;
                float v3 = acc[mt][nt][3] + bv1;
                if (relu) {
                    v0 = v0 > 0.f ? v0 : 0.f;  v1 = v1 > 0.f ? v1 : 0.f;
                    v2 = v2 > 0.f ? v2 : 0.f;  v3 = v3 > 0.f ? v3 : 0.f;
                }
                *(float2*)&C[(size_t)mrow0 * N + ncol]       = make_float2(v0, v1);
                *(float2*)&C[(size_t)(mrow0 + 8) * N + ncol] = make_float2(v2, v3);
            }
        }
    }
}

// ---------------- persistent LSTM recurrence ---------------------------------
__device__ __forceinline__ float sigf(float x) { return 1.f / (1.f + expf(-x)); }

template<int N>
__device__ __forceinline__ void reduce_stage(float* acc, int lane, int ofs)
{
    bool hi = (lane & ofs) != 0;
    #pragma unroll
    for (int i = 0; i < N; i++) {
        float send = hi ? acc[i] : acc[i + N];
        float recv = __shfl_xor_sync(0xffffffffu, send, ofs);
        float keep = hi ? acc[i + N] : acc[i];
        acc[i] = keep + recv;
    }
}

__global__ void __launch_bounds__(256, 2) lstm_persistent(
    const float* __restrict__ hq0, const float* __restrict__ cq0,
    const float* __restrict__ hk0, const float* __restrict__ ck0,
    const float* __restrict__ Wh_q, const float* __restrict__ bh_q,
    const float* __restrict__ Wh_k, const float* __restrict__ bh_k,
    float* __restrict__ out)
{
    __shared__ float hs[SB][SD + 4];
    int cta  = blockIdx.x;
    int lstm = cta >> 7;
    int ublk = (cta & 127) * 8;

    const float* Wh  = lstm ? Wh_k : Wh_q;
    const float* bh  = lstm ? bh_k : bh_q;
    const float* gx  = lstm ? g_gxk : g_gxq;
    float*       hss = lstm ? g_hks : g_hqs;
    const float* h0  = lstm ? hk0 : hq0;
    const float* c0  = lstm ? ck0 : cq0;

    int tid = threadIdx.x;
    int w = tid >> 5, lane = tid & 31;
    int u = ublk + w;
    int gate = lane >> 3, b = lane & 7;
    int r = gate * SD + u;
    float bhr = bh[r];

    const float* wbase0 = Wh + ((size_t)(0 * SD + u)) * SD + lane * 4;
    const float* wbase1 = Wh + ((size_t)(1 * SD + u)) * SD + lane * 4;
    const float* wbase2 = Wh + ((size_t)(2 * SD + u)) * SD + lane * 4;
    const float* wbase3 = Wh + ((size_t)(3 * SD + u)) * SD + lane * 4;

    float creg = 0.f, hlast = 0.f;
    if (lane < 8) creg = c0[b * SD + u];

    int sense = 0;
    const int nblk = gridDim.x;
    unsigned mask = 0xffffffffu;

    for (int t = 0; t < SS; t++) {
        const float* hin = (t == 0) ? h0 : g_h[lstm][t & 1];

        float gxv = __ldcg(&gx[((size_t)b * SS + t) * SG + r]);

        for (int i = tid * 4; i < SB * SD; i += 1024) {
            float4 v = __ldcg((const float4*)(hin + i));
            *(float4*)&hs[i >> 10][i & 1023] = v;
        }
        __syncthreads();

        float acc[32];
        #pragma unroll
        for (int i = 0; i < 32; i++) acc[i] = 0.f;

        #pragma unroll
        for (int it = 0; it < 8; it++) {
            float4 hv[8];
            #pragma unroll
            for (int bb = 0; bb < 8; bb++)
                hv[bb] = *(const float4*)&hs[bb][it * 128 + lane * 4];

            float4 wv0 = *(const float4*)(wbase0 + it * 128);
            float4 wv1 = *(const float4*)(wbase1 + it * 128);
            float4 wv2 = *(const float4*)(wbase2 + it * 128);
            float4 wv3 = *(const float4*)(wbase3 + it * 128);

            #pragma unroll
            for (int bb = 0; bb < 8; bb++) {
                acc[0 * 8 + bb] += wv0.x * hv[bb].x + wv0.y * hv[bb].y
                                 + wv0.z * hv[bb].z + wv0.w * hv[bb].w;
                acc[1 * 8 + bb] += wv1.x * hv[bb].x + wv1.y * hv[bb].y
                                 + wv1.z * hv[bb].z + wv1.w * hv[bb].w;
                acc[2 * 8 + bb] += wv2.x * hv[bb].x + wv2.y * hv[bb].y
                                 + wv2.z * hv[bb].z + wv2.w * hv[bb].w;
                acc[3 * 8 + bb] += wv3.x * hv[bb].x + wv3.y * hv[bb].y
                                 + wv3.z * hv[bb].z + wv3.w * hv[bb].w;
            }
        }

        reduce_stage<16>(acc, lane, 16);
        reduce_stage<8>(acc, lane, 8);
        reduce_stage<4>(acc, lane, 4);
        reduce_stage<2>(acc, lane, 2);
        reduce_stage<1>(acc, lane, 1);

        float a = acc[0] + gxv + bhr;

        float gi = __shfl_sync(mask, a, b);
        float gf = __shfl_sync(mask, a, 8 + b);
        float gg = __shfl_sync(mask, a, 16 + b);
        float go = __shfl_sync(mask, a, 24 + b);

        if (lane < 8) {
            float cn = sigf(gf) * creg + sigf(gi) * tanhf(gg);
            float hn = sigf(go) * tanhf(cn);
            creg = cn;
            hlast = hn;
            g_h[lstm][(t & 1) ^ 1][b * SD + u] = hn;
            hss[((size_t)b * SS + t) * SD + u] = hn;
        }

        __syncthreads();
        if (tid == 0) {
            sense ^= 1;
            __threadfence();
            if (atomicAdd((int*)&g_bar_count, 1) == nblk - 1) {
                g_bar_count = 0;
                __threadfence();
                g_bar_sense = sense;
            } else {
                while (g_bar_sense != sense) { }
            }
            __threadfence();
        }
        __syncthreads();
    }

    if (lane < 8) {
        const size_t base = (size_t)MTOT * SQD + (size_t)MTOT * SKD;
        out[base + (size_t)lstm * 2 * SB * SD + b * SD + u] = hlast;
        out[base + (size_t)lstm * 2 * SB * SD + SB * SD + b * SD + u] = creg;
    }
}

// ---------------- barrier init -----------------------------------------------
__global__ void init_barrier()
{
    if (threadIdx.x == 0 && blockIdx.x == 0) {
        g_bar_count = 0;
        g_bar_sense = 0;
    }
}

// ---------------- launch ------------------------------------------------------
extern "C" void kernel_launch(void* const* d_in, const int* in_sizes, int n_in,
                              void* d_out, int out_size)
{
    const float* x    = (const float*)d_in[0];
    const float* hq   = (const float*)d_in[1];
    const float* cq   = (const float*)d_in[2];
    const float* hk   = (const float*)d_in[3];
    const float* ck   = (const float*)d_in[4];
    const float* Wi_q = (const float*)d_in[5];
    const float* Wh_q = (const float*)d_in[6];
    const float* bi_q = (const float*)d_in[7];
    const float* bh_q = (const float*)d_in[8];
    const float* Wi_k = (const float*)d_in[9];
    const float* Wh_k = (const float*)d_in[10];
    const float* bi_k = (const float*)d_in[11];
    const float* bh_k = (const float*)d_in[12];
    const float* W1_q = (const float*)d_in[13];
    const float* b1_q = (const float*)d_in[14];
    const float* W2_q = (const float*)d_in[15];
    const float* b2_q = (const float*)d_in[16];
    const float* W1_k = (const float*)d_in[17];
    const float* b1_k = (const float*)d_in[18];
    const float* W2_k = (const float*)d_in[19];
    const float* b2_k = (const float*)d_in[20];
    float* out = (float*)d_out;

    float *gxq, *gxk, *hqs, *hks, *t1q, *t1k, *xr, *wq, *wk;
    cudaGetSymbolAddress((void**)&gxq, g_gxq);
    cudaGetSymbolAddress((void**)&gxk, g_gxk);
    cudaGetSymbolAddress((void**)&hqs, g_hqs);
    cudaGetSymbolAddress((void**)&hks, g_hks);
    cudaGetSymbolAddress((void**)&t1q, g_t1q);
    cudaGetSymbolAddress((void**)&t1k, g_t1k);
    cudaGetSymbolAddress((void**)&xr, g_xr);
    cudaGetSymbolAddress((void**)&wq, g_wq);
    cudaGetSymbolAddress((void**)&wk, g_wk);

    init_barrier<<<1, 32>>>();

    // Pre-round big GEMM operands to tf32 (removes cvt from GEMM mainloop)
    {
        int n4x = MTOT * SD / 4;
        round_tf32_k<<<(n4x + 255) / 256, 256>>>((const float4*)x, (float4*)xr, n4x);
        int n4w = SG * SD / 4;
        round_tf32_k<<<(n4w + 255) / 256, 256>>>((const float4*)Wi_q, (float4*)wq, n4w);
        round_tf32_k<<<(n4w + 255) / 256, 256>>>((const float4*)Wi_k, (float4*)wk, n4w);
    }

    // Hoisted input projections: gx = x @ Wi^T + bi  (M=16384, N=4096, K=1024)
    dim3 ggx(SG / 128, MTOT / 128);
    tf32gemm_pipe<0><<<ggx, 256>>>(xr, wq, bi_q, gxq, MTOT, SG, SD, 0);
    tf32gemm_pipe<0><<<ggx, 256>>>(xr, wk, bi_k, gxk, MTOT, SG, SD, 0);

    // Full recurrence in ONE launch
    lstm_persistent<<<256, 256>>>(hq, cq, hk, ck, Wh_q, bh_q, Wh_k, bh_k, out);

    // Output MLPs
    tf32gemm_pipe<1><<<dim3(1, MTOT / 128), 256>>>(hqs, W1_q, b1_q, t1q, MTOT, SOH, SD, 1);
    tf32gemm_pipe<1><<<dim3(SQD / 128, MTOT / 128), 256>>>(t1q, W2_q, b2_q, out, MTOT, SQD, SOH, 0);
    tf32gemm_pipe<1><<<dim3(1, MTOT / 128), 256>>>(hks, W1_k, b1_k, t1k, MTOT, SOH, SD, 1);
    tf32gemm_pipe<1><<<dim3(SKD / 128, MTOT / 128), 256>>>(t1k, W2_k, b2_k,
                                                           out + (size_t)MTOT * SQD, MTOT, SKD, SOH, 0);
}